// round 15
// baseline (speedup 1.0000x reference)
#include <cuda_runtime.h>
#include <cuda_bf16.h>
#include <cstdint>

// ---------------- problem constants ----------------
#define NX       51380224            // 32*128*112*112
#define NW       147456              // 128*128*3*3
#define HW       12544               // 112*112
#define WDIM     112
#define CIN      128
#define COUT     128
#define KK       9

#define PW       114                 // padded width/height
#define PHW      12996               // 114*114

#define GROUP    36

// scratch (static device globals)
__device__ __nv_bfloat16 g_xp[32L * PHW * CIN];       // quantized bf16, padded NHWC
__device__ __nv_bfloat16 g_w[KK * COUT * CIN];        // quantized bf16, [k][co][ci]

// ---------------- helpers ----------------
__device__ __forceinline__ uint32_t smem_u32(const void* p) {
    uint32_t a;
    asm("{ .reg .u64 t; cvta.to.shared.u64 t, %1; cvt.u32.u64 %0, t; }" : "=r"(a) : "l"(p));
    return a;
}

__device__ __forceinline__ void cp_async16(uint32_t dst, const void* src, uint32_t src_bytes) {
    asm volatile("cp.async.cg.shared.global [%0], [%1], 16, %2;"
                 :: "r"(dst), "l"(src), "r"(src_bytes) : "memory");
}
#define CP_COMMIT()  asm volatile("cp.async.commit_group;" ::: "memory")
#define CP_WAIT(n)   asm volatile("cp.async.wait_group %0;" :: "n"(n) : "memory")

__device__ __forceinline__ void ldmatrix_x4(uint32_t* r, uint32_t addr) {
    asm volatile("ldmatrix.sync.aligned.m8n8.x4.shared.b16 {%0,%1,%2,%3}, [%4];"
                 : "=r"(r[0]), "=r"(r[1]), "=r"(r[2]), "=r"(r[3]) : "r"(addr));
}

__device__ __forceinline__ void mma_bf16(float* d, const uint32_t* a, const uint32_t* b) {
    asm volatile(
        "mma.sync.aligned.m16n8k16.row.col.f32.bf16.bf16.f32 "
        "{%0,%1,%2,%3}, {%4,%5,%6,%7}, {%8,%9}, {%0,%1,%2,%3};"
        : "+f"(d[0]), "+f"(d[1]), "+f"(d[2]), "+f"(d[3])
        : "r"(a[0]), "r"(a[1]), "r"(a[2]), "r"(a[3]), "r"(b[0]), "r"(b[1]));
}

// ---------------- quantization ----------------
__device__ __forceinline__ float bfp_q(float v, float inv_step, float step) {
    float q = rintf(v * inv_step);            // exact (power-of-2 mul), half-to-even
    q = fminf(fmaxf(q, -128.0f), 127.0f);
    return q * step;                          // exact
}

// quant_w: 4096 groups of 36 (exact); writes bf16 transposed [k][co][ci]
__global__ void quant_w_kernel(const float* __restrict__ w) {
    int grp = blockIdx.x * blockDim.x + threadIdx.x;
    if (grp >= NW / GROUP) return;
    const float* p = w + grp * GROUP;

    float mx = 0.0f;
#pragma unroll
    for (int i = 0; i < GROUP; i++) mx = fmaxf(mx, fabsf(p[i]));

    float st = 0.0f, inv = 0.0f;
    bool nz = (mx > 0.0f);
    if (nz) {
        int e = ilogbf(mx);
        st  = exp2f((float)(e - 7));
        inv = exp2f((float)(7 - e));
    }
#pragma unroll
    for (int i = 0; i < GROUP; i++) {
        int f  = grp * GROUP + i;
        int co = f / (CIN * KK);
        int r  = f % (CIN * KK);
        int ci = r / KK;
        int k  = r % KK;
        float q = nz ? bfp_q(p[i], inv, st) : 0.0f;
        g_w[k * (COUT * CIN) + co * CIN + ci] = __float2bfloat16(q);
    }
}

// ---------------- zero the padded border of g_xp ----------------
__global__ void border_zero_kernel() {
    int u = blockIdx.x * 256 + threadIdx.x;       // < 32*452*16 = 231424
    int c8 = u & 15;
    int v = u >> 4;
    int pos = v % 452, b = v / 452;
    int p;
    if (pos < 228) {                               // top/bottom rows
        int rr = pos / 114, cc = pos % 114;
        p = (rr ? 113 * PW : 0) + cc;
    } else {                                       // left/right cols
        int j = pos - 228;
        int cc = (j < 112) ? 0 : 113;
        int hh = (j < 112 ? j : j - 112) + 1;
        p = hh * PW + cc;
    }
    *(uint4*)(g_xp + ((long)b * PHW + p) * CIN + c8 * 8) = make_uint4(0, 0, 0, 0);
}

// ---------------- fused BFP-quantize + NCHW->padded-NHWC transpose ----------------
// Block: (b, 64-px tile). For each of 128 ci, load the 136-float group-extended
// fp32 segment [f-36, f+100) (f = flat NCHW index of first px), compute the 2-3
// group scales covering the window, quantize, stage bf16 in swizzled smem, and
// write padded NHWC with uint4 stores. Bit-exact vs. separate quant+transpose.
#define FSEG   136
#define SEG_B  (128 * FSEG * 4)          // 69632
#define SINV_B (128 * 3 * 4)             // 1536
#define SM2_OFF (SEG_B + 2 * SINV_B)     // seg + sinv + sstep
#define QT_SMEM (SM2_OFF + 128 * 72 * 2) // + 18432 = 91136 B

__global__ void __launch_bounds__(256) quant_transpose_kernel(const float* __restrict__ x) {
    extern __shared__ __align__(16) char qsm[];
    float* seg   = (float*)qsm;                         // [128][FSEG]
    float* sinv  = (float*)(qsm + SEG_B);               // [128][3]
    float* sstep = (float*)(qsm + SEG_B + SINV_B);      // [128][3]
    __nv_bfloat16* sm2 = (__nv_bfloat16*)(qsm + SM2_OFF); // [128][72]

    const int tid = threadIdx.x;
    const int b   = blockIdx.x / 196;
    const int p0  = (blockIdx.x % 196) * 64;

    // ---- load: 128 ci x 34 float4 (segment [f-36, f+100), f = (b*128+ci)*HW + p0)
#pragma unroll
    for (int i = 0; i < 17; i++) {
        int v = tid + i * 256;                 // < 4352
        int ci = v / 34, j4 = v % 34;
        long f = ((long)(b * CIN + ci)) * HW + p0;
        long idx = f - 36 + (long)j4 * 4;
        float4 val;
        if (idx >= 0 && idx + 3 < NX) {
            val = *(const float4*)(x + idx);
        } else {
            float* vp = (float*)&val;
#pragma unroll
            for (int k = 0; k < 4; k++)
                vp[k] = (idx + k >= 0 && idx + k < NX) ? x[idx + k] : 0.0f;
        }
        *(float4*)(seg + ci * FSEG + j4 * 4) = val;
    }
    __syncthreads();

    // ---- group scales: up to 3 groups per ci
    for (int u = tid; u < 384; u += 256) {
        int ci = u / 3, sl = u % 3;
        long f = ((long)(b * CIN + ci)) * HW + p0;
        int r0 = (int)(f % 36);
        int gcount = (r0 + 63) / 36 + 1;       // groups covering px [0,64)
        if (sl < gcount) {
            int off = 36 - r0 + 36 * sl;       // group start within segment
            const float* gp = seg + ci * FSEG + off;
            float mx = 0.0f;
#pragma unroll
            for (int k = 0; k < GROUP; k++) mx = fmaxf(mx, fabsf(gp[k]));
            float iv = 0.0f, st = 0.0f;
            if (mx > 0.0f) {
                int e = ilogbf(mx);
                st = exp2f((float)(e - 7));
                iv = exp2f((float)(7 - e));
            }
            sinv[ci * 3 + sl]  = iv;           // iv=st=0 -> q = 0 exactly
            sstep[ci * 3 + sl] = st;
        }
    }
    __syncthreads();

    // ---- quantize 32 px per thread, stage bf16 swizzled
    {
        int ci = tid >> 1;
        int pb = (tid & 1) * 32;
        long f = ((long)(b * CIN + ci)) * HW + p0;
        int r0 = (int)(f % 36);
        const float* sp = seg + ci * FSEG + 36;
        const int key = ((ci >> 3) & 7) << 3;
        __nv_bfloat16* op = sm2 + ci * 72;
#pragma unroll
        for (int k = 0; k < 32; k++) {
            int p = pb + k;
            int slot = (r0 + p) / 36;
            float q = bfp_q(sp[p], sinv[ci * 3 + slot], sstep[ci * 3 + slot]);
            op[p ^ key] = __float2bfloat16(q);
        }
    }
    __syncthreads();

    // ---- write out: padded NHWC, uint4 per (px, 8ci)
#pragma unroll
    for (int i = 0; i < 4; i++) {
        int u = tid + i * 256;
        int px = u >> 4, s2 = u & 15;
        __nv_bfloat16 tmp[8];
        int col = px ^ ((s2 & 7) << 3);
#pragma unroll
        for (int j = 0; j < 8; j++) tmp[j] = sm2[(s2 * 8 + j) * 72 + col];
        int s = p0 + px;
        long p = s + 2 * (s / WDIM) + PW + 1;
        *(uint4*)(g_xp + ((long)b * PHW + p) * CIN + s2 * 8) = *(const uint4*)tmp;
    }
}

// ---------------- HMMA implicit-GEMM conv with halo reuse (R9 + 5-stage ring) ----------------
// CTA: 128 Cout x 128 px, 256 threads = 8 warps (2M x 4N), warp tile 64x32.
// Outer: 4 ci-quarters; inner: 9 taps. 36 sections, 1 sync each.
// A: [tap][128co][32ci] streamed via 5-stage ring, prefetch 4 ahead, wait(3).
// B: 360-row strip per ci-quarter (6 slices of 256 cp.asyncs), shared by 9 taps,
//    double-buffered, drip-loaded at sections t<6 of the prior quarter.
#define APITCH  80
#define A_STG   (128 * APITCH)       // 10240 B
#define NSTG    5
#define B_ROWS  360
#define B_TILE  (B_ROWS * APITCH)    // 28800 B
#define SMEM_SZ (NSTG * A_STG + 2 * B_TILE)   // 108800 B

__global__ void __launch_bounds__(256, 2) conv_hmma_kernel(const float* __restrict__ bias,
                                                           float* __restrict__ out) {
    extern __shared__ __align__(16) char smem[];
    char* Bbuf = smem + NSTG * A_STG;

    const int tid  = threadIdx.x;
    const int lane = tid & 31, wid = tid >> 5;
    const int wm = wid >> 2, wn = wid & 3;        // warp grid 2x4
    const int b  = blockIdx.x / 98;
    const int s0 = (blockIdx.x % 98) * 128;
    const int h0 = s0 / WDIM;
    const int pbase = s0 + 2 * h0;                // = p(s0) - (PW+1)

    // A loader: row = tid>>1, 32B half = (tid&1)
    const int arow = tid >> 1;
    const int alo  = tid & 1;
    uint32_t dA[NSTG];
#pragma unroll
    for (int s = 0; s < NSTG; s++)
        dA[s] = smem_u32(smem + s * A_STG + arow * APITCH + alo * 32);
    const uint32_t bBufAddr = smem_u32(Bbuf);
    const long xpb = (long)b * PHW * CIN;

    auto issueA = [&](int c, int stg) {
        int q = c / 9, t = c - q * 9;
        const __nv_bfloat16* src = g_w + t * (COUT * CIN) + arow * CIN + q * 32 + alo * 16;
        cp_async16(dA[stg],      src,     16u);
        cp_async16(dA[stg] + 16, src + 8, 16u);
    };
    auto issueB = [&](int qq, int slice) {
        int idx = slice * 256 + tid;
        if (idx < B_ROWS * 4) {
            int row = idx >> 2, ch = idx & 3;
            uint32_t dst = bBufAddr + (uint32_t)((qq & 1) * B_TILE + row * APITCH + ch * 16);
            const __nv_bfloat16* src = g_xp + xpb + (long)(pbase + row) * CIN + qq * 32 + ch * 8;
            cp_async16(dst, src, 16u);
        }
    };

    float acc[4][4][4];
#pragma unroll
    for (int i = 0; i < 4; i++)
#pragma unroll
        for (int j = 0; j < 4; j++)
#pragma unroll
            for (int q = 0; q < 4; q++) acc[i][j][q] = 0.0f;

    // prologue: group0 = B[0] strip + A[0]; then A[1], A[2], A[3]
    for (int s = 0; s < 6; s++) issueB(0, s);
    issueA(0, 0); CP_COMMIT();
    issueA(1, 1); CP_COMMIT();
    issueA(2, 2); CP_COMMIT();
    issueA(3, 3); CP_COMMIT();

    // per-lane fragment bases
    const uint32_t aRow = (uint32_t)((wm * 64 + (lane & 15)) * APITCH + (lane >> 4) * 16);
    const uint32_t s0addr = smem_u32(smem);
    const int i0 = wn * 32 + (lane & 7) + ((lane >> 4) << 3);
    const int i1 = i0 + 16;
    const int prel0 = i0 + 2 * ((s0 + i0) / WDIM - h0) + (PW + 1);
    const int prel1 = i1 + 2 * ((s0 + i1) / WDIM - h0) + (PW + 1);
    const uint32_t bChunk = bBufAddr + (uint32_t)(((lane >> 3) & 1) * 16);

    int stg = 0;                                  // = c % 5
    int stg4 = 4;                                 // = (c+4) % 5
    for (int c = 0; c < 36; c++) {
        const int q = c / 9, t = c - q * 9;
        CP_WAIT(3);
        __syncthreads();
        if (c + 4 < 36) issueA(c + 4, stg4);
        if (t < 6 && q < 3) issueB(q + 1, t);
        CP_COMMIT();

        const int dh = t / 3 - 1, dw = t % 3 - 1;
        const int tapoff = dh * PW + dw;
        const uint32_t baseA = s0addr + (uint32_t)(stg * A_STG) + aRow;
        const uint32_t bq = bChunk + (uint32_t)((q & 1) * B_TILE);
        const uint32_t b0 = bq + (uint32_t)((prel0 + tapoff) * APITCH);
        const uint32_t b1 = bq + (uint32_t)((prel1 + tapoff) * APITCH);

#pragma unroll
        for (int ks = 0; ks < 2; ks++) {
            uint32_t afr[4][4];
#pragma unroll
            for (int i = 0; i < 4; i++)
                ldmatrix_x4(afr[i], baseA + i * 16 * APITCH + ks * 32);
            uint32_t bfr[2][4];
            ldmatrix_x4(bfr[0], b0 + ks * 32);
            ldmatrix_x4(bfr[1], b1 + ks * 32);
#pragma unroll
            for (int i = 0; i < 4; i++)
#pragma unroll
                for (int j = 0; j < 4; j++)
                    mma_bf16(acc[i][j], afr[i], &bfr[j >> 1][(j & 1) * 2]);
        }
        stg  = (stg  + 1 == NSTG) ? 0 : stg  + 1;
        stg4 = (stg4 + 1 == NSTG) ? 0 : stg4 + 1;
    }

    // epilogue: rows co = wm*64+i*16+{lane>>2,+8}; cols px = wn*32+j*8+(lane&3)*2
    float* ob = out + (long)b * (COUT * HW) + s0;
#pragma unroll
    for (int i = 0; i < 4; i++) {
        int r0 = wm * 64 + i * 16 + (lane >> 2);
        int r1 = r0 + 8;
        float bv0 = __ldg(&bias[r0]);
        float bv1 = __ldg(&bias[r1]);
        float* p0 = ob + (long)r0 * HW;
        float* p1 = ob + (long)r1 * HW;
#pragma unroll
        for (int j = 0; j < 4; j++) {
            int col = wn * 32 + j * 8 + (lane & 3) * 2;
            *(float2*)(p0 + col) = make_float2(acc[i][j][0] + bv0, acc[i][j][1] + bv0);
            *(float2*)(p1 + col) = make_float2(acc[i][j][2] + bv1, acc[i][j][3] + bv1);
        }
    }
}

// ---------------- launch ----------------
extern "C" void kernel_launch(void* const* d_in, const int* in_sizes, int n_in,
                              void* d_out, int out_size) {
    const float* x    = (const float*)d_in[0];
    const float* wgt  = (const float*)d_in[1];
    const float* bias = (const float*)d_in[2];
    float* out = (float*)d_out;

    cudaFuncSetAttribute(conv_hmma_kernel,
                         cudaFuncAttributeMaxDynamicSharedMemorySize, SMEM_SZ);
    cudaFuncSetAttribute(quant_transpose_kernel,
                         cudaFuncAttributeMaxDynamicSharedMemorySize, QT_SMEM);

    quant_w_kernel<<<(NW / GROUP + 255) / 256, 256>>>(wgt);
    border_zero_kernel<<<904, 256>>>();
    quant_transpose_kernel<<<32 * 196, 256, QT_SMEM>>>(x);
    conv_hmma_kernel<<<32 * 98, 256, SMEM_SZ>>>(bias, out);
}

// round 16
// speedup vs baseline: 1.4499x; 1.4499x over previous
#include <cuda_runtime.h>
#include <cuda_bf16.h>
#include <cstdint>

// ---------------- problem constants ----------------
#define NX       51380224            // 32*128*112*112
#define NW       147456              // 128*128*3*3
#define HW       12544               // 112*112
#define WDIM     112
#define CIN      128
#define COUT     128
#define KK       9

#define PW       114                 // padded width/height
#define PHW      12996               // 114*114

#define GROUP    36
#define EPB      9216                // elems per quant block (256 groups)

#define NTILES   3136                // 32 batches x 98 px-tiles
#define PGRID    304                 // persistent CTAs (2/SM x 152)

// scratch (static device globals)
__device__ __nv_bfloat16 g_xn[NX];                    // quantized bf16, NCHW
__device__ __nv_bfloat16 g_xp[32L * PHW * CIN];       // quantized bf16, padded NHWC
__device__ __nv_bfloat16 g_w[KK * COUT * CIN];        // quantized bf16, [k][co][ci]

// ---------------- helpers ----------------
__device__ __forceinline__ uint32_t smem_u32(const void* p) {
    uint32_t a;
    asm("{ .reg .u64 t; cvta.to.shared.u64 t, %1; cvt.u32.u64 %0, t; }" : "=r"(a) : "l"(p));
    return a;
}

__device__ __forceinline__ void cp_async16(uint32_t dst, const void* src, uint32_t src_bytes) {
    asm volatile("cp.async.cg.shared.global [%0], [%1], 16, %2;"
                 :: "r"(dst), "l"(src), "r"(src_bytes) : "memory");
}
#define CP_COMMIT()  asm volatile("cp.async.commit_group;" ::: "memory")
#define CP_WAIT(n)   asm volatile("cp.async.wait_group %0;" :: "n"(n) : "memory")

__device__ __forceinline__ void ldmatrix_x4(uint32_t* r, uint32_t addr) {
    asm volatile("ldmatrix.sync.aligned.m8n8.x4.shared.b16 {%0,%1,%2,%3}, [%4];"
                 : "=r"(r[0]), "=r"(r[1]), "=r"(r[2]), "=r"(r[3]) : "r"(addr));
}

__device__ __forceinline__ void mma_bf16(float* d, const uint32_t* a, const uint32_t* b) {
    asm volatile(
        "mma.sync.aligned.m16n8k16.row.col.f32.bf16.bf16.f32 "
        "{%0,%1,%2,%3}, {%4,%5,%6,%7}, {%8,%9}, {%0,%1,%2,%3};"
        : "+f"(d[0]), "+f"(d[1]), "+f"(d[2]), "+f"(d[3])
        : "r"(a[0]), "r"(a[1]), "r"(a[2]), "r"(a[3]), "r"(b[0]), "r"(b[1]));
}

// ---------------- quantization ----------------
__device__ __forceinline__ float bfp_q(float v, float inv_step, float step) {
    float q = rintf(v * inv_step);            // exact (power-of-2 mul), half-to-even
    q = fminf(fmaxf(q, -128.0f), 127.0f);
    return q * step;                          // exact
}

// quant_x: block = 9216 contiguous elems = 256 groups; writes bf16 NCHW
__global__ void __launch_bounds__(256) quant_x_kernel(const float* __restrict__ x) {
    __shared__ float sm[EPB];
    const long base = (long)blockIdx.x * EPB;
    const int tid = threadIdx.x;

    const float4* xv = (const float4*)(x + base);
    float4* smv = (float4*)sm;
    if (base + EPB <= NX) {
#pragma unroll
        for (int i = 0; i < 9; i++) smv[tid + i * 256] = xv[tid + i * 256];
    } else {
        for (int i = 0; i < 9; i++) {
            int e4 = tid + i * 256;
            long e = base + (long)e4 * 4;
            float4 v = make_float4(0.f, 0.f, 0.f, 0.f);
            if (e + 3 < NX) v = xv[e4];
            else {
                float* vp = (float*)&v;
                for (int j = 0; j < 4; j++) if (e + j < NX) vp[j] = x[e + j];
            }
            smv[e4] = v;
        }
    }
    __syncthreads();

    const float* g = sm + tid * GROUP;
    float mx = 0.0f;
#pragma unroll
    for (int i = 0; i < GROUP; i++) mx = fmaxf(mx, fabsf(g[i]));

    __nv_bfloat16* ob = (__nv_bfloat16*)((char*)sm + (size_t)tid * (GROUP * 4));
    if (mx > 0.0f) {
        int e = ilogbf(mx);
        float st  = exp2f((float)(e - 7));
        float inv = exp2f((float)(7 - e));
#pragma unroll
        for (int i = 0; i < GROUP; i++) ob[i] = __float2bfloat16(bfp_q(g[i], inv, st));
    } else {
#pragma unroll
        for (int i = 0; i < GROUP; i++) ob[i] = __float2bfloat16(0.0f);
    }
    __syncthreads();

    for (int j = 0; j < 9; j++) {
        int m = tid + j * 256;
        int t2 = m / 9, sub = m % 9;
        uint2 v = *(const uint2*)((char*)sm + (size_t)t2 * 144 + (size_t)sub * 8);
        long e0 = base + (long)m * 4;
        if (e0 + 3 < NX) {
            *(uint2*)(g_xn + e0) = v;
        } else {
            const __nv_bfloat16* vp = (const __nv_bfloat16*)&v;
            for (int q = 0; q < 4; q++) if (e0 + q < NX) g_xn[e0 + q] = vp[q];
        }
    }
}

// quant_w: 4096 groups of 36 (exact); writes bf16 transposed [k][co][ci]
__global__ void quant_w_kernel(const float* __restrict__ w) {
    int grp = blockIdx.x * blockDim.x + threadIdx.x;
    if (grp >= NW / GROUP) return;
    const float* p = w + grp * GROUP;

    float mx = 0.0f;
#pragma unroll
    for (int i = 0; i < GROUP; i++) mx = fmaxf(mx, fabsf(p[i]));

    float st = 0.0f, inv = 0.0f;
    bool nz = (mx > 0.0f);
    if (nz) {
        int e = ilogbf(mx);
        st  = exp2f((float)(e - 7));
        inv = exp2f((float)(7 - e));
    }
#pragma unroll
    for (int i = 0; i < GROUP; i++) {
        int f  = grp * GROUP + i;
        int co = f / (CIN * KK);
        int r  = f % (CIN * KK);
        int ci = r / KK;
        int k  = r % KK;
        float q = nz ? bfp_q(p[i], inv, st) : 0.0f;
        g_w[k * (COUT * CIN) + co * CIN + ci] = __float2bfloat16(q);
    }
}

// ---------------- zero the padded border of g_xp ----------------
__global__ void border_zero_kernel() {
    int u = blockIdx.x * 256 + threadIdx.x;       // < 32*452*16 = 231424
    int c8 = u & 15;
    int v = u >> 4;
    int pos = v % 452, b = v / 452;
    int p;
    if (pos < 228) {                               // top/bottom rows
        int rr = pos / 114, cc = pos % 114;
        p = (rr ? 113 * PW : 0) + cc;
    } else {                                       // left/right cols
        int j = pos - 228;
        int cc = (j < 112) ? 0 : 113;
        int hh = (j < 112 ? j : j - 112) + 1;
        p = hh * PW + cc;
    }
    *(uint4*)(g_xp + ((long)b * PHW + p) * CIN + c8 * 8) = make_uint4(0, 0, 0, 0);
}

// ---------------- NCHW -> padded NHWC bf16 transpose ----------------
__global__ void __launch_bounds__(256) transpose_x_kernel() {
    __shared__ __nv_bfloat16 sm[128 * 72];
    const int tid = threadIdx.x;
    const int blk = blockIdx.x;
    const int b = blk / 196;
    const int p0 = (blk % 196) * 64;

#pragma unroll
    for (int i = 0; i < 4; i++) {
        int u = tid + i * 256;
        int ci = u >> 3, seg = u & 7;
        uint4 v = *(const uint4*)(g_xn + ((long)(b * CIN + ci) * HW + p0 + seg * 8));
        int col = (seg * 8) ^ (((ci >> 3) & 7) << 3);
        *(uint4*)(&sm[ci * 72 + col]) = v;
    }
    __syncthreads();

#pragma unroll
    for (int i = 0; i < 4; i++) {
        int u = tid + i * 256;
        int px = u >> 4, s2 = u & 15;
        __nv_bfloat16 tmp[8];
        int col = px ^ ((s2 & 7) << 3);
#pragma unroll
        for (int j = 0; j < 8; j++) tmp[j] = sm[(s2 * 8 + j) * 72 + col];
        int s = p0 + px;                         // flat 112x112 index
        long p = s + 2 * (s / WDIM) + PW + 1;    // padded flat index
        *(uint4*)(g_xp + ((long)b * PHW + p) * CIN + s2 * 8) = *(const uint4*)tmp;
    }
}

// ---------------- HMMA implicit-GEMM conv: halo reuse + persistent CTAs ----------------
// Grid: 304 persistent CTAs (2/SM) looping over 3136 tiles.
// Per tile: 128 Cout x 128 px, 8 warps (2M x 4N), warp tile 64x32.
// Outer: 4 ci-quarters; inner: 9 taps. 36 sections, 1 sync each.
// A: [tap][128co][32ci] via 4-stage ring, prefetch 3 ahead, wait(2).
// B: 360-row strip per quarter, shared by 9 taps, double-buffered, 6 drip slices.
#define APITCH  80
#define A_STG   (128 * APITCH)       // 10240 B
#define NSTG    4
#define B_ROWS  360
#define B_TILE  (B_ROWS * APITCH)    // 28800 B
#define SMEM_SZ (NSTG * A_STG + 2 * B_TILE)   // 98560 B

__global__ void __launch_bounds__(256, 2) conv_hmma_kernel(const float* __restrict__ bias,
                                                           float* __restrict__ out) {
    extern __shared__ __align__(16) char smem[];
    char* Bbuf = smem + NSTG * A_STG;

    const int tid  = threadIdx.x;
    const int lane = tid & 31, wid = tid >> 5;
    const int wm = wid >> 2, wn = wid & 3;        // warp grid 2x4

    // A loader: row = tid>>1, 32B half = (tid&1)
    const int arow = tid >> 1;
    const int alo  = tid & 1;
    uint32_t dA[NSTG];
#pragma unroll
    for (int s = 0; s < NSTG; s++)
        dA[s] = smem_u32(smem + s * A_STG + arow * APITCH + alo * 32);
    const uint32_t bBufAddr = smem_u32(Bbuf);

    // per-lane constants
    const uint32_t aRow = (uint32_t)((wm * 64 + (lane & 15)) * APITCH + (lane >> 4) * 16);
    const uint32_t s0addr = smem_u32(smem);
    const int i0 = wn * 32 + (lane & 7) + ((lane >> 4) << 3);
    const int i1 = i0 + 16;
    const uint32_t bChunk = bBufAddr + (uint32_t)(((lane >> 3) & 1) * 16);
    const float bv0a[4] = { __ldg(&bias[wm * 64 + 0 * 16 + (lane >> 2)]),
                            __ldg(&bias[wm * 64 + 1 * 16 + (lane >> 2)]),
                            __ldg(&bias[wm * 64 + 2 * 16 + (lane >> 2)]),
                            __ldg(&bias[wm * 64 + 3 * 16 + (lane >> 2)]) };
    const float bv1a[4] = { __ldg(&bias[wm * 64 + 0 * 16 + (lane >> 2) + 8]),
                            __ldg(&bias[wm * 64 + 1 * 16 + (lane >> 2) + 8]),
                            __ldg(&bias[wm * 64 + 2 * 16 + (lane >> 2) + 8]),
                            __ldg(&bias[wm * 64 + 3 * 16 + (lane >> 2) + 8]) };

    for (int tile = blockIdx.x; tile < NTILES; tile += PGRID) {
        const int b  = tile / 98;
        const int s0 = (tile % 98) * 128;
        const int h0 = s0 / WDIM;
        const int pbase = s0 + 2 * h0;            // = p(s0) - (PW+1)
        const long xpb = (long)b * PHW * CIN;

        const int prel0 = i0 + 2 * ((s0 + i0) / WDIM - h0) + (PW + 1);
        const int prel1 = i1 + 2 * ((s0 + i1) / WDIM - h0) + (PW + 1);

        // guard: all warps done reading smem of the previous tile
        __syncthreads();

        // prologue: group0 = B[0] strip (6 slices) + A[0]; then A[1], A[2]
#pragma unroll
        for (int s = 0; s < 6; s++) {
            int idx = s * 256 + tid;
            if (idx < B_ROWS * 4) {
                int row = idx >> 2, ch = idx & 3;
                cp_async16(bBufAddr + (uint32_t)(row * APITCH + ch * 16),
                           g_xp + xpb + (long)(pbase + row) * CIN + ch * 8, 16u);
            }
        }
        {
            const __nv_bfloat16* src = g_w + arow * CIN + alo * 16;  // tap 0, q 0
            cp_async16(dA[0],      src,     16u);
            cp_async16(dA[0] + 16, src + 8, 16u);
        }
        CP_COMMIT();
#pragma unroll
        for (int c = 1; c <= 2; c++) {
            const __nv_bfloat16* src = g_w + c * (COUT * CIN) + arow * CIN + alo * 16;
            cp_async16(dA[c],      src,     16u);
            cp_async16(dA[c] + 16, src + 8, 16u);
            CP_COMMIT();
        }

        float acc[4][4][4];
#pragma unroll
        for (int i = 0; i < 4; i++)
#pragma unroll
            for (int j = 0; j < 4; j++)
#pragma unroll
                for (int q = 0; q < 4; q++) acc[i][j][q] = 0.0f;

        for (int c = 0; c < 36; c++) {
            const int q = c / 9, t = c - q * 9;
            CP_WAIT(2);
            __syncthreads();
            if (c + 3 < 36) {
                int cn = c + 3, qn = cn / 9, tn = cn - qn * 9;
                const __nv_bfloat16* src =
                    g_w + tn * (COUT * CIN) + arow * CIN + qn * 32 + alo * 16;
                cp_async16(dA[cn & 3],      src,     16u);
                cp_async16(dA[cn & 3] + 16, src + 8, 16u);
            }
            if (t < 6 && q < 3) {
                int idx = t * 256 + tid;
                if (idx < B_ROWS * 4) {
                    int row = idx >> 2, ch = idx & 3;
                    uint32_t dst = bBufAddr +
                        (uint32_t)(((q + 1) & 1) * B_TILE + row * APITCH + ch * 16);
                    cp_async16(dst,
                        g_xp + xpb + (long)(pbase + row) * CIN + (q + 1) * 32 + ch * 8, 16u);
                }
            }
            CP_COMMIT();

            const int dh = t / 3 - 1, dw = t % 3 - 1;
            const int tapoff = dh * PW + dw;
            const uint32_t baseA = s0addr + (uint32_t)((c & 3) * A_STG) + aRow;
            const uint32_t bq = bChunk + (uint32_t)((q & 1) * B_TILE);
            const uint32_t b0 = bq + (uint32_t)((prel0 + tapoff) * APITCH);
            const uint32_t b1 = bq + (uint32_t)((prel1 + tapoff) * APITCH);

#pragma unroll
            for (int ks = 0; ks < 2; ks++) {
                uint32_t afr[4][4];
#pragma unroll
                for (int i = 0; i < 4; i++)
                    ldmatrix_x4(afr[i], baseA + i * 16 * APITCH + ks * 32);
                uint32_t bfr[2][4];
                ldmatrix_x4(bfr[0], b0 + ks * 32);
                ldmatrix_x4(bfr[1], b1 + ks * 32);
#pragma unroll
                for (int i = 0; i < 4; i++)
#pragma unroll
                    for (int j = 0; j < 4; j++)
                        mma_bf16(acc[i][j], afr[i], &bfr[j >> 1][(j & 1) * 2]);
            }
        }

        // epilogue
        float* ob = out + (long)b * (COUT * HW) + s0;
#pragma unroll
        for (int i = 0; i < 4; i++) {
            int r0 = wm * 64 + i * 16 + (lane >> 2);
            int r1 = r0 + 8;
            float* p0 = ob + (long)r0 * HW;
            float* p1 = ob + (long)r1 * HW;
#pragma unroll
            for (int j = 0; j < 4; j++) {
                int col = wn * 32 + j * 8 + (lane & 3) * 2;
                *(float2*)(p0 + col) = make_float2(acc[i][j][0] + bv0a[i], acc[i][j][1] + bv0a[i]);
                *(float2*)(p1 + col) = make_float2(acc[i][j][2] + bv1a[i], acc[i][j][3] + bv1a[i]);
            }
        }
    }
}

// ---------------- launch ----------------
extern "C" void kernel_launch(void* const* d_in, const int* in_sizes, int n_in,
                              void* d_out, int out_size) {
    const float* x    = (const float*)d_in[0];
    const float* wgt  = (const float*)d_in[1];
    const float* bias = (const float*)d_in[2];
    float* out = (float*)d_out;

    cudaFuncSetAttribute(conv_hmma_kernel,
                         cudaFuncAttributeMaxDynamicSharedMemorySize, SMEM_SZ);

    quant_x_kernel<<<(NX + EPB - 1) / EPB, 256>>>(x);
    quant_w_kernel<<<(NW / GROUP + 255) / 256, 256>>>(wgt);
    border_zero_kernel<<<904, 256>>>();
    transpose_x_kernel<<<32 * 196, 256>>>();
    conv_hmma_kernel<<<PGRID, 256, SMEM_SZ>>>(bias, out);
}

// round 17
// speedup vs baseline: 1.4839x; 1.0234x over previous
#include <cuda_runtime.h>
#include <cuda_bf16.h>
#include <cstdint>

// ---------------- problem constants ----------------
#define NX       51380224            // 32*128*112*112
#define NW       147456              // 128*128*3*3
#define HW       12544               // 112*112
#define WDIM     112
#define CIN      128
#define COUT     128
#define KK       9

#define PW       114                 // padded width/height
#define PHW      12996               // 114*114

#define GROUP    36
#define EPB      9216                // elems per quant block (256 groups)

// scratch (static device globals)
__device__ __nv_bfloat16 g_xn[NX];                    // quantized bf16, NCHW
// padded NHWC, QUARTER-MAJOR: [b][quarter(4)][PHW][ci32]
__device__ __nv_bfloat16 g_xp[32L * 4 * PHW * 32];
// weights, QUARTER-MAJOR: [tap][quarter(4)][co128][ci32]
__device__ __nv_bfloat16 g_w[KK * 4 * COUT * 32];

// ---------------- helpers ----------------
__device__ __forceinline__ uint32_t smem_u32(const void* p) {
    uint32_t a;
    asm("{ .reg .u64 t; cvta.to.shared.u64 t, %1; cvt.u32.u64 %0, t; }" : "=r"(a) : "l"(p));
    return a;
}

__device__ __forceinline__ void cp_async16(uint32_t dst, const void* src, uint32_t src_bytes) {
    asm volatile("cp.async.cg.shared.global [%0], [%1], 16, %2;"
                 :: "r"(dst), "l"(src), "r"(src_bytes) : "memory");
}
#define CP_COMMIT()  asm volatile("cp.async.commit_group;" ::: "memory")
#define CP_WAIT(n)   asm volatile("cp.async.wait_group %0;" :: "n"(n) : "memory")

__device__ __forceinline__ void ldmatrix_x4(uint32_t* r, uint32_t addr) {
    asm volatile("ldmatrix.sync.aligned.m8n8.x4.shared.b16 {%0,%1,%2,%3}, [%4];"
                 : "=r"(r[0]), "=r"(r[1]), "=r"(r[2]), "=r"(r[3]) : "r"(addr));
}

__device__ __forceinline__ void mma_bf16(float* d, const uint32_t* a, const uint32_t* b) {
    asm volatile(
        "mma.sync.aligned.m16n8k16.row.col.f32.bf16.bf16.f32 "
        "{%0,%1,%2,%3}, {%4,%5,%6,%7}, {%8,%9}, {%0,%1,%2,%3};"
        : "+f"(d[0]), "+f"(d[1]), "+f"(d[2]), "+f"(d[3])
        : "r"(a[0]), "r"(a[1]), "r"(a[2]), "r"(a[3]), "r"(b[0]), "r"(b[1]));
}

// ---------------- quantization ----------------
__device__ __forceinline__ float bfp_q(float v, float inv_step, float step) {
    float q = rintf(v * inv_step);            // exact (power-of-2 mul), half-to-even
    q = fminf(fmaxf(q, -128.0f), 127.0f);
    return q * step;                          // exact
}

// quant_x: block = 9216 contiguous elems = 256 groups; writes bf16 NCHW
__global__ void __launch_bounds__(256) quant_x_kernel(const float* __restrict__ x) {
    __shared__ float sm[EPB];
    const long base = (long)blockIdx.x * EPB;
    const int tid = threadIdx.x;

    const float4* xv = (const float4*)(x + base);
    float4* smv = (float4*)sm;
    if (base + EPB <= NX) {
#pragma unroll
        for (int i = 0; i < 9; i++) smv[tid + i * 256] = xv[tid + i * 256];
    } else {
        for (int i = 0; i < 9; i++) {
            int e4 = tid + i * 256;
            long e = base + (long)e4 * 4;
            float4 v = make_float4(0.f, 0.f, 0.f, 0.f);
            if (e + 3 < NX) v = xv[e4];
            else {
                float* vp = (float*)&v;
                for (int j = 0; j < 4; j++) if (e + j < NX) vp[j] = x[e + j];
            }
            smv[e4] = v;
        }
    }
    __syncthreads();

    const float* g = sm + tid * GROUP;
    float mx = 0.0f;
#pragma unroll
    for (int i = 0; i < GROUP; i++) mx = fmaxf(mx, fabsf(g[i]));

    __nv_bfloat16* ob = (__nv_bfloat16*)((char*)sm + (size_t)tid * (GROUP * 4));
    if (mx > 0.0f) {
        int e = ilogbf(mx);
        float st  = exp2f((float)(e - 7));
        float inv = exp2f((float)(7 - e));
#pragma unroll
        for (int i = 0; i < GROUP; i++) ob[i] = __float2bfloat16(bfp_q(g[i], inv, st));
    } else {
#pragma unroll
        for (int i = 0; i < GROUP; i++) ob[i] = __float2bfloat16(0.0f);
    }
    __syncthreads();

    for (int j = 0; j < 9; j++) {
        int m = tid + j * 256;
        int t2 = m / 9, sub = m % 9;
        uint2 v = *(const uint2*)((char*)sm + (size_t)t2 * 144 + (size_t)sub * 8);
        long e0 = base + (long)m * 4;
        if (e0 + 3 < NX) {
            *(uint2*)(g_xn + e0) = v;
        } else {
            const __nv_bfloat16* vp = (const __nv_bfloat16*)&v;
            for (int q = 0; q < 4; q++) if (e0 + q < NX) g_xn[e0 + q] = vp[q];
        }
    }
}

// quant_w: 4096 groups of 36 (exact); writes bf16 quarter-major [k][q][co][ci32]
__global__ void quant_w_kernel(const float* __restrict__ w) {
    int grp = blockIdx.x * blockDim.x + threadIdx.x;
    if (grp >= NW / GROUP) return;
    const float* p = w + grp * GROUP;

    float mx = 0.0f;
#pragma unroll
    for (int i = 0; i < GROUP; i++) mx = fmaxf(mx, fabsf(p[i]));

    float st = 0.0f, inv = 0.0f;
    bool nz = (mx > 0.0f);
    if (nz) {
        int e = ilogbf(mx);
        st  = exp2f((float)(e - 7));
        inv = exp2f((float)(7 - e));
    }
#pragma unroll
    for (int i = 0; i < GROUP; i++) {
        int f  = grp * GROUP + i;
        int co = f / (CIN * KK);
        int r  = f % (CIN * KK);
        int ci = r / KK;
        int k  = r % KK;
        float q = nz ? bfp_q(p[i], inv, st) : 0.0f;
        g_w[(k * 4 + (ci >> 5)) * (COUT * 32) + co * 32 + (ci & 31)] = __float2bfloat16(q);
    }
}

// ---------------- zero the padded border of g_xp (quarter-major) ----------------
__global__ void border_zero_kernel() {
    int u = blockIdx.x * 256 + threadIdx.x;       // < 32*452*16 = 231424
    int c8 = u & 15;                               // quarter = c8>>2, part = c8&3
    int v = u >> 4;
    int pos = v % 452, b = v / 452;
    int p;
    if (pos < 228) {                               // top/bottom rows
        int rr = pos / 114, cc = pos % 114;
        p = (rr ? 113 * PW : 0) + cc;
    } else {                                       // left/right cols
        int j = pos - 228;
        int cc = (j < 112) ? 0 : 113;
        int hh = (j < 112 ? j : j - 112) + 1;
        p = hh * PW + cc;
    }
    *(uint4*)(g_xp + ((long)(b * 4 + (c8 >> 2)) * PHW + p) * 32 + (c8 & 3) * 8) =
        make_uint4(0, 0, 0, 0);
}

// ---------------- NCHW -> padded quarter-major NHWC bf16 transpose ----------------
__global__ void __launch_bounds__(256) transpose_x_kernel() {
    __shared__ __nv_bfloat16 sm[128 * 72];
    const int tid = threadIdx.x;
    const int blk = blockIdx.x;
    const int b = blk / 196;
    const int p0 = (blk % 196) * 64;

#pragma unroll
    for (int i = 0; i < 4; i++) {
        int u = tid + i * 256;
        int ci = u >> 3, seg = u & 7;
        uint4 v = *(const uint4*)(g_xn + ((long)(b * CIN + ci) * HW + p0 + seg * 8));
        int col = (seg * 8) ^ (((ci >> 3) & 7) << 3);
        *(uint4*)(&sm[ci * 72 + col]) = v;
    }
    __syncthreads();

#pragma unroll
    for (int i = 0; i < 4; i++) {
        int u = tid + i * 256;
        int px = u >> 4, s2 = u & 15;
        __nv_bfloat16 tmp[8];
        int col = px ^ ((s2 & 7) << 3);
#pragma unroll
        for (int j = 0; j < 8; j++) tmp[j] = sm[(s2 * 8 + j) * 72 + col];
        int s = p0 + px;                         // flat 112x112 index
        long p = s + 2 * (s / WDIM) + PW + 1;    // padded flat index
        *(uint4*)(g_xp + ((long)(b * 4 + (s2 >> 2)) * PHW + p) * 32 + (s2 & 3) * 8) =
            *(const uint4*)tmp;
    }
}

// ---------------- HMMA implicit-GEMM conv with halo reuse (R9 + contiguous L2) ----------------
// CTA: 128 Cout x 128 px, 256 threads = 8 warps (2M x 4N), warp tile 64x32.
// Outer: 4 ci-quarters; inner: 9 taps. 36 sections, 1 sync each.
// A: [tap][q][128co][32ci] quarter-major -> warp reads 512B contiguous (100% sectors).
// B: quarter-major strip rows of 64B -> warp reads 512B contiguous (100% sectors).
#define APITCH  80
#define A_STG   (128 * APITCH)       // 10240 B
#define NSTG    4
#define B_ROWS  360
#define B_TILE  (B_ROWS * APITCH)    // 28800 B
#define SMEM_SZ (NSTG * A_STG + 2 * B_TILE)   // 98560 B

__global__ void __launch_bounds__(256, 2) conv_hmma_kernel(const float* __restrict__ bias,
                                                           float* __restrict__ out) {
    extern __shared__ __align__(16) char smem[];
    char* Bbuf = smem + NSTG * A_STG;

    const int tid  = threadIdx.x;
    const int lane = tid & 31, wid = tid >> 5;
    const int wm = wid >> 2, wn = wid & 3;        // warp grid 2x4
    const int b  = blockIdx.x / 98;
    const int s0 = (blockIdx.x % 98) * 128;
    const int h0 = s0 / WDIM;
    const int pbase = s0 + 2 * h0;                // = p(s0) - (PW+1)

    // A loader: row = tid>>1, 32B half = (tid&1)
    const int arow = tid >> 1;
    const int alo  = tid & 1;
    uint32_t dA[NSTG];
#pragma unroll
    for (int s = 0; s < NSTG; s++)
        dA[s] = smem_u32(smem + s * A_STG + arow * APITCH + alo * 32);
    const uint32_t bBufAddr = smem_u32(Bbuf);
    const long xpb = (long)b * 4 * PHW * 32;      // quarter-major batch base

    auto issueA = [&](int c, int stg) {
        int q = c / 9, t = c - q * 9;
        const __nv_bfloat16* src = g_w + (t * 4 + q) * (COUT * 32) + arow * 32 + alo * 16;
        cp_async16(dA[stg],      src,     16u);
        cp_async16(dA[stg] + 16, src + 8, 16u);
    };
    auto issueB = [&](int qq, int slice) {
        int idx = slice * 256 + tid;
        if (idx < B_ROWS * 4) {
            int row = idx >> 2, ch = idx & 3;
            uint32_t dst = bBufAddr + (uint32_t)((qq & 1) * B_TILE + row * APITCH + ch * 16);
            const __nv_bfloat16* src =
                g_xp + xpb + ((long)qq * PHW + pbase + row) * 32 + ch * 8;
            cp_async16(dst, src, 16u);
        }
    };

    float acc[4][4][4];
#pragma unroll
    for (int i = 0; i < 4; i++)
#pragma unroll
        for (int j = 0; j < 4; j++)
#pragma unroll
            for (int q = 0; q < 4; q++) acc[i][j][q] = 0.0f;

    // prologue: all of B[0] + A[0] as group0, then A[1], A[2]
    for (int s = 0; s < 6; s++) issueB(0, s);
    issueA(0, 0); CP_COMMIT();
    issueA(1, 1); CP_COMMIT();
    issueA(2, 2); CP_COMMIT();

    // per-lane fragment bases
    const uint32_t aRow = (uint32_t)((wm * 64 + (lane & 15)) * APITCH + (lane >> 4) * 16);
    const uint32_t s0addr = smem_u32(smem);
    const int i0 = wn * 32 + (lane & 7) + ((lane >> 4) << 3);
    const int i1 = i0 + 16;
    const int prel0 = i0 + 2 * ((s0 + i0) / WDIM - h0) + (PW + 1);
    const int prel1 = i1 + 2 * ((s0 + i1) / WDIM - h0) + (PW + 1);
    const uint32_t bChunk = bBufAddr + (uint32_t)(((lane >> 3) & 1) * 16);

    for (int c = 0; c < 36; c++) {
        const int q = c / 9, t = c - q * 9;
        CP_WAIT(2);
        __syncthreads();
        if (c + 3 < 36) issueA(c + 3, (c + 3) & 3);
        if (t < 6 && q < 3) issueB(q + 1, t);
        CP_COMMIT();

        const int dh = t / 3 - 1, dw = t % 3 - 1;
        const int tapoff = dh * PW + dw;
        const uint32_t baseA = s0addr + (uint32_t)((c & 3) * A_STG) + aRow;
        const uint32_t bq = bChunk + (uint32_t)((q & 1) * B_TILE);
        const uint32_t b0 = bq + (uint32_t)((prel0 + tapoff) * APITCH);
        const uint32_t b1 = bq + (uint32_t)((prel1 + tapoff) * APITCH);

#pragma unroll
        for (int ks = 0; ks < 2; ks++) {
            uint32_t afr[4][4];
#pragma unroll
            for (int i = 0; i < 4; i++)
                ldmatrix_x4(afr[i], baseA + i * 16 * APITCH + ks * 32);
            uint32_t bfr[2][4];
            ldmatrix_x4(bfr[0], b0 + ks * 32);
            ldmatrix_x4(bfr[1], b1 + ks * 32);
#pragma unroll
            for (int i = 0; i < 4; i++)
#pragma unroll
                for (int j = 0; j < 4; j++)
                    mma_bf16(acc[i][j], afr[i], &bfr[j >> 1][(j & 1) * 2]);
        }
    }

    // epilogue: rows co = wm*64+i*16+{lane>>2,+8}; cols px = wn*32+j*8+(lane&3)*2
    float* ob = out + (long)b * (COUT * HW) + s0;
#pragma unroll
    for (int i = 0; i < 4; i++) {
        int r0 = wm * 64 + i * 16 + (lane >> 2);
        int r1 = r0 + 8;
        float bv0 = __ldg(&bias[r0]);
        float bv1 = __ldg(&bias[r1]);
        float* p0 = ob + (long)r0 * HW;
        float* p1 = ob + (long)r1 * HW;
#pragma unroll
        for (int j = 0; j < 4; j++) {
            int col = wn * 32 + j * 8 + (lane & 3) * 2;
            *(float2*)(p0 + col) = make_float2(acc[i][j][0] + bv0, acc[i][j][1] + bv0);
            *(float2*)(p1 + col) = make_float2(acc[i][j][2] + bv1, acc[i][j][3] + bv1);
        }
    }
}

// ---------------- launch ----------------
extern "C" void kernel_launch(void* const* d_in, const int* in_sizes, int n_in,
                              void* d_out, int out_size) {
    const float* x    = (const float*)d_in[0];
    const float* wgt  = (const float*)d_in[1];
    const float* bias = (const float*)d_in[2];
    float* out = (float*)d_out;

    cudaFuncSetAttribute(conv_hmma_kernel,
                         cudaFuncAttributeMaxDynamicSharedMemorySize, SMEM_SZ);

    quant_x_kernel<<<(NX + EPB - 1) / EPB, 256>>>(x);
    quant_w_kernel<<<(NW / GROUP + 255) / 256, 256>>>(wgt);
    border_zero_kernel<<<904, 256>>>();
    transpose_x_kernel<<<32 * 196, 256>>>();
    conv_hmma_kernel<<<32 * 98, 256, SMEM_SZ>>>(bias, out);
}